// round 2
// baseline (speedup 1.0000x reference)
#include <cuda_runtime.h>
#include <math.h>

#define KC 64
#define DD 8
#define NC 36
#define CSTRIDE 48
#define NBLOCKS 128
#define NTHREADS 256
#define BPT 4
#define BTOT 131072

__device__ __align__(16) float g_coeff[KC * CSTRIDE];
__device__ float g_partials[NBLOCKS];

__device__ __forceinline__ float ex2f(float x) {
    float y; asm("ex2.approx.ftz.f32 %0, %1;" : "=f"(y) : "f"(x)); return y;
}
__device__ __forceinline__ float lg2f(float x) {
    float y; asm("lg2.approx.f32 %0, %1;" : "=f"(y) : "f"(x)); return y;
}

// ---------------------------------------------------------------------------
// Prep: per-component k, build scaled inverse-Cholesky coefficients (fp64).
//   A  = L^{-1} * sqrt(0.5/ln2)          (36 packed lower-tri entries)
//   nw = -A @ mu                          (8)
//   c2n = -(norm_const - logdet)/ln2      (1, negated -> M-accumulator init)
// ---------------------------------------------------------------------------
__global__ void prep_kernel(const float* __restrict__ mu,
                            const float* __restrict__ Lc) {
    int k = threadIdx.x;
    if (k >= KC) return;

    double L[DD][DD];
    int m = 0;
    for (int i = 0; i < DD; i++)
        for (int j = 0; j <= i; j++)
            L[i][j] = (double)Lc[k * NC + m++];

    // invert lower-triangular L
    double X[DD][DD];
    for (int j = 0; j < DD; j++) {
        X[j][j] = 1.0 / L[j][j];
        for (int i = j + 1; i < DD; i++) {
            double s = 0.0;
            for (int t = j; t < i; t++) s += L[i][t] * X[t][j];
            X[i][j] = -s / L[i][i];
        }
    }
    double logdet = 0.0;
    for (int i = 0; i < DD; i++) logdet += log(L[i][i]);

    const double LN2 = 0.6931471805599453;
    const double NORMC = -4.0 * log(2.0 * 3.14159265358979323846); // -0.5*D*log(2pi)
    double scale = sqrt(0.5 / LN2);

    float* out = g_coeff + k * CSTRIDE;
    m = 0;
    for (int i = 0; i < DD; i++)
        for (int j = 0; j <= i; j++)
            out[m++] = (float)(X[i][j] * scale);
    for (int i = 0; i < DD; i++) {
        double acc = 0.0;
        for (int j = 0; j <= i; j++) acc += X[i][j] * (double)mu[k * DD + j];
        out[36 + i] = (float)(-scale * acc);
    }
    out[44] = (float)(-(NORMC - logdet) / LN2);  // negated c2
    out[45] = 0.0f; out[46] = 0.0f; out[47] = 0.0f;
}

// ---------------------------------------------------------------------------
// Main: each thread handles BPT=4 rows b. Online base-2 logsumexp over k.
//   z_i   = nw_i + sum_{j<=i} A_ij * t_j         (36 FMA)
//   macc  = c2n + sum z_i^2                      (8 FMA)  == 0.5*M/ln2 - c2
//   w     = log2(pi + 1e-10) - macc              (weighted / ln2)
// ---------------------------------------------------------------------------
__global__ void __launch_bounds__(NTHREADS)
main_kernel(const float* __restrict__ pi, const float* __restrict__ target) {
    __shared__ __align__(16) float sc[KC * CSTRIDE];
    __shared__ float red[NTHREADS];

    // stage coefficients to smem
    {
        const float4* gsrc = (const float4*)g_coeff;
        float4* sdst = (float4*)sc;
        for (int i = threadIdx.x; i < KC * CSTRIDE / 4; i += NTHREADS)
            sdst[i] = gsrc[i];
    }
    __syncthreads();

    const int b0 = blockIdx.x * (NTHREADS * BPT) + threadIdx.x;

    float t[BPT][DD];
#pragma unroll
    for (int r = 0; r < BPT; r++) {
        const int b = b0 + r * NTHREADS;
        float4 v0 = ((const float4*)(target + (size_t)b * DD))[0];
        float4 v1 = ((const float4*)(target + (size_t)b * DD))[1];
        t[r][0] = v0.x; t[r][1] = v0.y; t[r][2] = v0.z; t[r][3] = v0.w;
        t[r][4] = v1.x; t[r][5] = v1.y; t[r][6] = v1.z; t[r][7] = v1.w;
    }

    float mx[BPT], sm[BPT];
#pragma unroll
    for (int r = 0; r < BPT; r++) { mx[r] = -1e30f; sm[r] = 0.0f; }

#pragma unroll 1
    for (int kt = 0; kt < KC / 4; kt++) {
        // pi tile: 4 consecutive k per b
        float p[BPT][4];
#pragma unroll
        for (int r = 0; r < BPT; r++) {
            const int b = b0 + r * NTHREADS;
            float4 pv = *((const float4*)(pi + (size_t)b * KC + kt * 4));
            p[r][0] = pv.x; p[r][1] = pv.y; p[r][2] = pv.z; p[r][3] = pv.w;
        }
#pragma unroll
        for (int kk = 0; kk < 4; kk++) {
            const float* c = sc + (kt * 4 + kk) * CSTRIDE;
#pragma unroll
            for (int r = 0; r < BPT; r++) {
                float z[DD];
#pragma unroll
                for (int i = 0; i < DD; i++) {
                    float acc = c[36 + i];
#pragma unroll
                    for (int j = 0; j <= i; j++)
                        acc = fmaf(c[i * (i + 1) / 2 + j], t[r][j], acc);
                    z[i] = acc;
                }
                float macc = c[44];
#pragma unroll
                for (int i = 0; i < DD; i++) macc = fmaf(z[i], z[i], macc);

                float lp = lg2f(p[r][kk] + 1e-10f);
                float w = lp - macc;
                float mn = fmaxf(mx[r], w);
                sm[r] = fmaf(sm[r], ex2f(mx[r] - mn), ex2f(w - mn));
                mx[r] = mn;
            }
        }
    }

    float part = 0.0f;
#pragma unroll
    for (int r = 0; r < BPT; r++) part += mx[r] + lg2f(sm[r]);

    red[threadIdx.x] = part;
    __syncthreads();
#pragma unroll
    for (int s = NTHREADS / 2; s > 0; s >>= 1) {
        if (threadIdx.x < s) red[threadIdx.x] += red[threadIdx.x + s];
        __syncthreads();
    }
    if (threadIdx.x == 0) g_partials[blockIdx.x] = red[0];
}

// ---------------------------------------------------------------------------
// Final deterministic reduction to the scalar NLL.
// ---------------------------------------------------------------------------
__global__ void reduce_kernel(float* __restrict__ out) {
    __shared__ float red[NBLOCKS];
    int tid = threadIdx.x;
    red[tid] = g_partials[tid];
    __syncthreads();
    for (int s = NBLOCKS / 2; s > 0; s >>= 1) {
        if (tid < s) red[tid] += red[tid + s];
        __syncthreads();
    }
    if (tid == 0)
        out[0] = (float)(-0.6931471805599453 * (double)red[0] / (double)BTOT);
}

extern "C" void kernel_launch(void* const* d_in, const int* in_sizes, int n_in,
                              void* d_out, int out_size) {
    const float* pi = (const float*)d_in[0];
    const float* mu = (const float*)d_in[1];
    const float* Lc = (const float*)d_in[2];
    const float* target = (const float*)d_in[3];

    prep_kernel<<<1, KC>>>(mu, Lc);
    main_kernel<<<NBLOCKS, NTHREADS>>>(pi, target);
    reduce_kernel<<<1, NBLOCKS>>>((float*)d_out);
}

// round 3
// speedup vs baseline: 1.3961x; 1.3961x over previous
#include <cuda_runtime.h>
#include <math.h>

#define KC 64
#define DD 8
#define NC 36
#define CP 48
#define NBLOCKS 128
#define NTHREADS 256
#define BTOT 131072

typedef unsigned long long ull;

__device__ __align__(16) ull g_coeffp[KC * CP];
__device__ float g_partials[NBLOCKS];
__device__ unsigned g_count = 0;

__device__ __forceinline__ float ex2f(float x) {
    float y; asm("ex2.approx.ftz.f32 %0, %1;" : "=f"(y) : "f"(x)); return y;
}
__device__ __forceinline__ float lg2f(float x) {
    float y; asm("lg2.approx.f32 %0, %1;" : "=f"(y) : "f"(x)); return y;
}
__device__ __forceinline__ ull fma2(ull a, ull b, ull c) {
    ull d; asm("fma.rn.f32x2 %0, %1, %2, %3;" : "=l"(d) : "l"(a), "l"(b), "l"(c)); return d;
}
__device__ __forceinline__ ull pack2(float lo, float hi) {
    ull v; asm("mov.b64 %0, {%1, %2};" : "=l"(v) : "f"(lo), "f"(hi)); return v;
}
__device__ __forceinline__ void unpack2(float& lo, float& hi, ull v) {
    asm("mov.b64 {%0, %1}, %2;" : "=f"(lo), "=f"(hi) : "l"(v));
}
__device__ __forceinline__ ull dup(float x) {
    unsigned u = __float_as_uint(x);
    return (ull)u | ((ull)u << 32);
}

// ---------------------------------------------------------------------------
// Prep (fp32): A = L^{-1} * sqrt(0.5/ln2), nw = -A@mu,
// c2n = sum(log2(Lii)) + 4*log2(2pi). Stored as DUPLICATED f32 pairs (b64).
// ---------------------------------------------------------------------------
__global__ void prep_kernel(const float* __restrict__ mu,
                            const float* __restrict__ Lc) {
    int k = threadIdx.x;
    if (k >= KC) return;

    float L[DD][DD];
    int m = 0;
#pragma unroll
    for (int i = 0; i < DD; i++)
#pragma unroll
        for (int j = 0; j <= i; j++)
            L[i][j] = Lc[k * NC + m++];

    float X[DD][DD];
#pragma unroll
    for (int j = 0; j < DD; j++) {
        X[j][j] = 1.0f / L[j][j];
#pragma unroll
        for (int i = j + 1; i < DD; i++) {
            float s = 0.0f;
            for (int t = j; t < i; t++) s = fmaf(L[i][t], X[t][j], s);
            X[i][j] = -s / L[i][i];
        }
    }
    float sumlg2 = 0.0f;
#pragma unroll
    for (int i = 0; i < DD; i++) sumlg2 += lg2f(L[i][i]);

    const float SCALE = 0.8493218003f;        // sqrt(0.5/ln2)
    const float C4LOG2PI = 10.6059845179f;    // 4*log2(2*pi)
    float c2n = sumlg2 + C4LOG2PI;

    ull* out = g_coeffp + k * CP;
    m = 0;
#pragma unroll
    for (int i = 0; i < DD; i++)
#pragma unroll
        for (int j = 0; j <= i; j++)
            out[m++] = dup(X[i][j] * SCALE);
#pragma unroll
    for (int i = 0; i < DD; i++) {
        float acc = 0.0f;
#pragma unroll
        for (int j = 0; j <= i; j++) acc = fmaf(X[i][j], mu[k * DD + j], acc);
        out[36 + i] = dup(-SCALE * acc);
    }
    out[44] = dup(c2n);
    out[45] = 0; out[46] = 0; out[47] = 0;
}

// ---------------------------------------------------------------------------
// Main: 4 rows/thread packed as 2 f32x2 pairs. Online base-2 logsumexp.
// Final reduction folded in via last-block-done counter (deterministic).
// ---------------------------------------------------------------------------
__global__ void __launch_bounds__(NTHREADS)
main_kernel(const float* __restrict__ pi, const float* __restrict__ target,
            float* __restrict__ out) {
    __shared__ __align__(16) ull sc[KC * CP];      // 24 KB, duplicated coeffs
    __shared__ float red[NTHREADS];
    __shared__ bool s_last;

    // stage packed coefficients
    {
        const float4* gsrc = (const float4*)g_coeffp;
        float4* sdst = (float4*)sc;
#pragma unroll
        for (int i = threadIdx.x; i < KC * CP / 2; i += NTHREADS)
            sdst[i] = gsrc[i];
    }
    __syncthreads();

    const int tid = threadIdx.x;
    const int b0 = blockIdx.x * (NTHREADS * 4) + tid;

    // load 4 target rows, pack pairs (0,1) and (2,3)
    float t[4][DD];
#pragma unroll
    for (int r = 0; r < 4; r++) {
        const float4* tp = (const float4*)(target + (size_t)(b0 + r * NTHREADS) * DD);
        float4 v0 = tp[0], v1 = tp[1];
        t[r][0] = v0.x; t[r][1] = v0.y; t[r][2] = v0.z; t[r][3] = v0.w;
        t[r][4] = v1.x; t[r][5] = v1.y; t[r][6] = v1.z; t[r][7] = v1.w;
    }
    ull tp0[DD], tp1[DD];
#pragma unroll
    for (int j = 0; j < DD; j++) {
        tp0[j] = pack2(t[0][j], t[1][j]);
        tp1[j] = pack2(t[2][j], t[3][j]);
    }

    float mx[4], sm[4];
#pragma unroll
    for (int r = 0; r < 4; r++) { mx[r] = -1e30f; sm[r] = 0.0f; }

#pragma unroll 1
    for (int kt = 0; kt < KC / 4; kt++) {
        float p[4][4];
#pragma unroll
        for (int r = 0; r < 4; r++) {
            float4 pv = *((const float4*)(pi + (size_t)(b0 + r * NTHREADS) * KC + kt * 4));
            p[r][0] = pv.x; p[r][1] = pv.y; p[r][2] = pv.z; p[r][3] = pv.w;
        }
#pragma unroll
        for (int kk = 0; kk < 4; kk++) {
            const ull* c = sc + (kt * 4 + kk) * CP;
            ull z0[DD], z1[DD];
            int m = 0;
#pragma unroll
            for (int i = 0; i < DD; i++) {
                ull nw = c[36 + i];
                ull a0 = nw, a1 = nw;
#pragma unroll
                for (int j = 0; j <= i; j++) {
                    ull cc = c[m + j];
                    a0 = fma2(cc, tp0[j], a0);
                    a1 = fma2(cc, tp1[j], a1);
                }
                m += i + 1;
                z0[i] = a0; z1[i] = a1;
            }
            ull macc0 = c[44], macc1 = macc0;
#pragma unroll
            for (int i = 0; i < DD; i++) {
                macc0 = fma2(z0[i], z0[i], macc0);
                macc1 = fma2(z1[i], z1[i], macc1);
            }
            float mm[4];
            unpack2(mm[0], mm[1], macc0);
            unpack2(mm[2], mm[3], macc1);
#pragma unroll
            for (int r = 0; r < 4; r++) {
                float w = lg2f(p[r][kk] + 1e-10f) - mm[r];
                float mn = fmaxf(mx[r], w);
                sm[r] = fmaf(sm[r], ex2f(mx[r] - mn), ex2f(w - mn));
                mx[r] = mn;
            }
        }
    }

    float part = 0.0f;
#pragma unroll
    for (int r = 0; r < 4; r++) part += mx[r] + lg2f(sm[r]);

    red[tid] = part;
    __syncthreads();
#pragma unroll
    for (int s = NTHREADS / 2; s > 0; s >>= 1) {
        if (tid < s) red[tid] += red[tid + s];
        __syncthreads();
    }
    if (tid == 0) {
        g_partials[blockIdx.x] = red[0];
        __threadfence();
        unsigned done = atomicAdd(&g_count, 1u);
        s_last = (done == NBLOCKS - 1);
    }
    __syncthreads();

    if (s_last) {
        float v = (tid < NBLOCKS) ? g_partials[tid] : 0.0f;
        red[tid] = v;
        __syncthreads();
#pragma unroll
        for (int s = NTHREADS / 2; s > 0; s >>= 1) {
            if (tid < s) red[tid] += red[tid + s];
            __syncthreads();
        }
        if (tid == 0) {
            out[0] = (float)(-0.6931471805599453 * (double)red[0] / (double)BTOT);
            g_count = 0;   // reset for next graph replay
        }
    }
}

extern "C" void kernel_launch(void* const* d_in, const int* in_sizes, int n_in,
                              void* d_out, int out_size) {
    const float* pi = (const float*)d_in[0];
    const float* mu = (const float*)d_in[1];
    const float* Lc = (const float*)d_in[2];
    const float* target = (const float*)d_in[3];

    prep_kernel<<<1, KC>>>(mu, Lc);
    main_kernel<<<NBLOCKS, NTHREADS>>>(pi, target, (float*)d_out);
}